// round 4
// baseline (speedup 1.0000x reference)
#include <cuda_runtime.h>
#include <cuda.h>
#include <cstdint>

// SphArr: complex orthonormal Y_l^m, l<4, over 524288 points.
// Out per point: 16 (l,m) x (re,im) = 32 floats (128B row).
// R4: per-warp autonomous pipeline. Each warp handles 4 chunks of 32 points,
// double-buffered 4KB SW128 smem tiles, each drained by a warp-issued TMA
// tensor store (box 32x32). No __syncthreads; compute(c) overlaps TMA(c-1).

#define NPOINTS (8 * 256 * 256)
#define THREADS 256
#define WARPS_PER_BLOCK 8
#define CHUNKS_PER_WARP 4
#define NBLOCKS (NPOINTS / (THREADS * CHUNKS_PER_WARP))   // 512

// ---- per-point math: 8 float4 components of the 32-float output row ----
__device__ __forceinline__ void sph_point(float x, float y, float z, float4 v[8]) {
    const float rho2 = fmaf(x, x, y * y);
    const float r2   = fmaf(z, z, rho2);
    const float rinv = rsqrtf(r2);
    const float ct   = z * rinv;                       // cos(theta)

    const bool  ok     = rho2 > 0.0f;
    const float rhoinv = ok ? rsqrtf(rho2) : 0.0f;
    const float st     = rho2 * rhoinv * rinv;         // sin(theta) = sqrt(rho2)/r
    const float c1 = ok ? x * rhoinv : 1.0f;
    const float s1 = y * rhoinv;
    const float c2 = c1 * c1 - s1 * s1;
    const float s2 = 2.0f * c1 * s1;
    const float c3 = c1 * c2 - s1 * s2;
    const float s3 = s1 * c2 + c1 * s2;

    const float ct2 = ct * ct;
    const float st2 = st * st;

    // Associated Legendre with Condon-Shortley phase (matches reference).
    const float b11 = 0.34549414947133547f * (-st);
    const float re1 = b11 * c1, im1 = b11 * s1;

    const float b21 = 0.25751613468215834f * (-3.0f * ct * st);
    const float re21 = b21 * c1, im21 = b21 * s1;
    const float b22 = 0.12875806734107764f * (3.0f * st2);
    const float re22 = b22 * c2, im22 = b22 * s2;

    const float b31 = 0.21545345607610053f * (-1.5f * st * (5.0f * ct2 - 1.0f));
    const float re31 = b31 * c1, im31 = b31 * s1;
    const float b32 = 0.06813236509755226f * (15.0f * ct * st2);
    const float re32 = b32 * c2, im32 = b32 * s2;
    const float b33 = 0.027814921575518937f * (-15.0f * st2 * st);
    const float re33 = b33 * c3, im33 = b33 * s3;

    const float y00 = 0.28209479177387814f;
    const float y10 = 0.48860251190291992f * ct;
    const float y20 = 0.63078313050504009f * 0.5f * (3.0f * ct2 - 1.0f);
    const float y30 = 0.74635266518023113f * 0.5f * ct * (5.0f * ct2 - 3.0f);

    v[0] = make_float4(y00, 0.0f, -re1, im1);
    v[1] = make_float4(y10, 0.0f, re1, im1);
    v[2] = make_float4(re22, -im22, -re21, im21);
    v[3] = make_float4(y20, 0.0f, re21, im21);
    v[4] = make_float4(re22, im22, -re33, im33);
    v[5] = make_float4(re32, -im32, -re31, im31);
    v[6] = make_float4(y30, 0.0f, re31, im31);
    v[7] = make_float4(re32, im32, re33, im33);
}

// ---- fast path: per-warp double-buffered SW128 smem + warp-issued TMA ----
__global__ __launch_bounds__(THREADS) void sph_kernel_tma(
    const __grid_constant__ CUtensorMap tmap,
    const float* __restrict__ X) {
    // 8 warps x 2 buffers x (32 rows x 128B) = 64KB
    __shared__ __align__(1024) float4 sm[WARPS_PER_BLOCK * 2 * 32 * 8];

    const int lane = threadIdx.x & 31;
    const int warp = threadIdx.x >> 5;
    const unsigned warp_global = blockIdx.x * WARPS_PER_BLOCK + warp;
    const unsigned pt_base = warp_global * (32u * CHUNKS_PER_WARP);

    float4* const buf0 = sm + warp * 2 * 32 * 8;
    const int rot = lane & 7;
    const bool leader = (lane == 0);

#pragma unroll
    for (int c = 0; c < CHUNKS_PER_WARP; c++) {
        const unsigned p = pt_base + c * 32u + lane;
        const float x = X[3u * p + 0];
        const float y = X[3u * p + 1];
        const float z = X[3u * p + 2];
        float4 v[8];
        sph_point(x, y, z, v);

        // Backpressure: buffer (c&1) was last used by chunk c-2; make sure its
        // TMA has finished reading before overwriting (keep <=1 group pending).
        if (c >= 2) {
            if (leader)
                asm volatile("cp.async.bulk.wait_group.read 1;" ::: "memory");
        }
        __syncwarp();

        // SW128 swizzled STS: row=lane, slot q -> q ^ (lane&7); conflict-free.
        float4* row = buf0 + (c & 1) * 32 * 8 + lane * 8;
        row[0 ^ rot] = v[0];
        row[1 ^ rot] = v[1];
        row[2 ^ rot] = v[2];
        row[3 ^ rot] = v[3];
        row[4 ^ rot] = v[4];
        row[5 ^ rot] = v[5];
        row[6 ^ rot] = v[6];
        row[7 ^ rot] = v[7];
        asm volatile("fence.proxy.async.shared::cta;" ::: "memory");
        __syncwarp();

        if (leader) {
            uint32_t saddr;
            asm("{ .reg .u64 t; cvta.to.shared.u64 t, %1; cvt.u32.u64 %0, t; }"
                : "=r"(saddr)
                : "l"((const void*)(buf0 + (c & 1) * 32 * 8)));
            const int row0 = (int)(pt_base + c * 32u);
            asm volatile(
                "cp.async.bulk.tensor.2d.global.shared::cta.tile.bulk_group "
                "[%0, {%1, %2}], [%3];"
                :: "l"(&tmap), "r"(0), "r"(row0), "r"(saddr)
                : "memory");
            asm volatile("cp.async.bulk.commit_group;" ::: "memory");
        }
    }
    // Drain all outstanding TMA stores before block retire.
    if (leader)
        asm volatile("cp.async.bulk.wait_group 0;" ::: "memory");
}

// ---- fallback path: padded smem + coalesced float4 STG (proven ~15.1us) ----
__global__ __launch_bounds__(256) void sph_kernel_stg(const float* __restrict__ X,
                                                      float4* __restrict__ out) {
    __shared__ float4 smf[256 * 9];
    const int tid = threadIdx.x;
    const unsigned p = blockIdx.x * 256u + tid;
    float4 v[8];
    sph_point(X[3u * p + 0], X[3u * p + 1], X[3u * p + 2], v);
#pragma unroll
    for (int q = 0; q < 8; q++) smf[tid * 9 + q] = v[q];
    __syncthreads();
    float4* dst = out + (unsigned long long)blockIdx.x * 2048ull;
#pragma unroll
    for (int i = 0; i < 8; i++) {
        const int idx = tid + i * 256;
        dst[idx] = smf[(idx >> 3) * 9 + (idx & 7)];
    }
}

typedef CUresult (*EncodeFn)(
    CUtensorMap*, CUtensorMapDataType, cuuint32_t, void*,
    const cuuint64_t*, const cuuint64_t*, const cuuint32_t*, const cuuint32_t*,
    CUtensorMapInterleave, CUtensorMapSwizzle, CUtensorMapL2promotion,
    CUtensorMapFloatOOBfill);

extern "C" void kernel_launch(void* const* d_in, const int* in_sizes, int n_in,
                              void* d_out, int out_size) {
    const float* X = (const float*)d_in[0];

    void* fn = nullptr;
    cudaDriverEntryPointQueryResult qst = cudaDriverEntryPointSymbolNotFound;
    cudaError_t qerr = cudaGetDriverEntryPointByVersion(
        "cuTensorMapEncodeTiled", &fn, 12000, cudaEnableDefault, &qst);

    bool tma_ok = false;
    CUtensorMap tmap;
    if (qerr == cudaSuccess && qst == cudaDriverEntryPointSuccess && fn != nullptr) {
        EncodeFn encode = (EncodeFn)fn;
        cuuint64_t dims[2]    = {32, (cuuint64_t)NPOINTS};  // 32 f32 per row
        cuuint64_t strides[1] = {128};                      // 128B row stride
        cuuint32_t box[2]     = {32, 32};                   // 4KB tile
        cuuint32_t estr[2]    = {1, 1};
        CUresult r = encode(&tmap, CU_TENSOR_MAP_DATA_TYPE_FLOAT32, 2, d_out,
                            dims, strides, box, estr,
                            CU_TENSOR_MAP_INTERLEAVE_NONE,
                            CU_TENSOR_MAP_SWIZZLE_128B,
                            CU_TENSOR_MAP_L2_PROMOTION_L2_128B,
                            CU_TENSOR_MAP_FLOAT_OOB_FILL_NONE);
        tma_ok = (r == CUDA_SUCCESS);
    }

    if (tma_ok) {
        sph_kernel_tma<<<NBLOCKS, THREADS>>>(tmap, X);
    } else {
        sph_kernel_stg<<<NPOINTS / 256, 256>>>(X, (float4*)d_out);
    }
}

// round 5
// speedup vs baseline: 1.2851x; 1.2851x over previous
#include <cuda_runtime.h>
#include <cstdint>

// SphArr: complex orthonormal Y_l^m, l<4, over 524288 points.
// Out per point: 16 (l,m) x (re,im) = 32 floats (128B row).
// R5: 2 points per thread (ILP x2, MLP 6, one barrier per 2 points),
// padded-SMEM staging (conflict-free), coalesced float4 stream-out.

#define NPOINTS (8 * 256 * 256)
#define THREADS 128
#define PTS_PER_BLOCK (THREADS * 2)            // 256
#define NBLOCKS (NPOINTS / PTS_PER_BLOCK)      // 2048

// ---- per-point math: 8 float4 components of the 32-float output row ----
__device__ __forceinline__ void sph_point(float x, float y, float z, float4 v[8]) {
    const float rho2 = fmaf(x, x, y * y);
    const float r2   = fmaf(z, z, rho2);
    const float rinv = rsqrtf(r2);
    const float ct   = z * rinv;                       // cos(theta)

    const bool  ok     = rho2 > 0.0f;
    const float rhoinv = ok ? rsqrtf(rho2) : 0.0f;
    const float st     = rho2 * rhoinv * rinv;         // sin(theta) = sqrt(rho2)/r
    const float c1 = ok ? x * rhoinv : 1.0f;
    const float s1 = y * rhoinv;
    const float c2 = c1 * c1 - s1 * s1;
    const float s2 = 2.0f * c1 * s1;
    const float c3 = c1 * c2 - s1 * s2;
    const float s3 = s1 * c2 + c1 * s2;

    const float ct2 = ct * ct;
    const float st2 = st * st;

    // Associated Legendre with Condon-Shortley phase (matches reference).
    const float b11 = 0.34549414947133547f * (-st);
    const float re1 = b11 * c1, im1 = b11 * s1;

    const float b21 = 0.25751613468215834f * (-3.0f * ct * st);
    const float re21 = b21 * c1, im21 = b21 * s1;
    const float b22 = 0.12875806734107764f * (3.0f * st2);
    const float re22 = b22 * c2, im22 = b22 * s2;

    const float b31 = 0.21545345607610053f * (-1.5f * st * (5.0f * ct2 - 1.0f));
    const float re31 = b31 * c1, im31 = b31 * s1;
    const float b32 = 0.06813236509755226f * (15.0f * ct * st2);
    const float re32 = b32 * c2, im32 = b32 * s2;
    const float b33 = 0.027814921575518937f * (-15.0f * st2 * st);
    const float re33 = b33 * c3, im33 = b33 * s3;

    const float y00 = 0.28209479177387814f;
    const float y10 = 0.48860251190291992f * ct;
    const float y20 = 0.63078313050504009f * 0.5f * (3.0f * ct2 - 1.0f);
    const float y30 = 0.74635266518023113f * 0.5f * ct * (5.0f * ct2 - 3.0f);

    v[0] = make_float4(y00, 0.0f, -re1, im1);
    v[1] = make_float4(y10, 0.0f, re1, im1);
    v[2] = make_float4(re22, -im22, -re21, im21);
    v[3] = make_float4(y20, 0.0f, re21, im21);
    v[4] = make_float4(re22, im22, -re33, im33);
    v[5] = make_float4(re32, -im32, -re31, im31);
    v[6] = make_float4(y30, 0.0f, re31, im31);
    v[7] = make_float4(re32, im32, re33, im33);
}

__global__ __launch_bounds__(THREADS, 6) void sph_kernel(
    const float* __restrict__ X, float4* __restrict__ out) {
    // 256 rows x (8 used + 1 pad) float4 = 36,864 B. Stride-9 float4 rows:
    // bank = (36*row + 4q) mod 32 -> conflict-free for both STS and LDS phases.
    __shared__ float4 sm[PTS_PER_BLOCK * 9];

    const int tid = threadIdx.x;
    const unsigned base = blockIdx.x * (unsigned)PTS_PER_BLOCK;
    const unsigned pa = base + tid;             // point A -> smem row tid
    const unsigned pb = pa + THREADS;           // point B -> smem row tid+128

    // Batch all 6 input loads up front (MLP=6).
    const float xa = X[3u * pa + 0];
    const float ya = X[3u * pa + 1];
    const float za = X[3u * pa + 2];
    const float xb = X[3u * pb + 0];
    const float yb = X[3u * pb + 1];
    const float zb = X[3u * pb + 2];

    // Two independent math chains -> compiler interleaves (ILP x2).
    float4 va[8], vb[8];
    sph_point(xa, ya, za, va);
    sph_point(xb, yb, zb, vb);

#pragma unroll
    for (int q = 0; q < 8; q++) sm[tid * 9 + q] = va[q];
#pragma unroll
    for (int q = 0; q < 8; q++) sm[(tid + THREADS) * 9 + q] = vb[q];

    __syncthreads();

    // Coalesced stream-out: 2048 float4 per block, 16 iterations of 128 lanes.
    float4* dst = out + (unsigned long long)base * 8ull;
#pragma unroll
    for (int i = 0; i < 16; i++) {
        const int idx = tid + i * THREADS;
        dst[idx] = sm[(idx >> 3) * 9 + (idx & 7)];
    }
}

extern "C" void kernel_launch(void* const* d_in, const int* in_sizes, int n_in,
                              void* d_out, int out_size) {
    const float* X = (const float*)d_in[0];
    sph_kernel<<<NBLOCKS, THREADS>>>(X, (float4*)d_out);
}

// round 7
// speedup vs baseline: 1.3045x; 1.0151x over previous
#include <cuda_runtime.h>
#include <cuda.h>
#include <cstdint>

// SphArr: complex orthonormal Y_l^m, l<4, over 524288 points.
// Out per point: 16 (l,m) x (re,im) = 32 floats (128B row).
// R7 (= R6 retry, infra timeout): pipelined block: 4 chunks x 128 points, two
// 16KB SW128 buffers, TMA store per chunk, waits deferred to buffer reuse only.
// Keeps many TMA drains in flight per SM, overlapped with compute; input
// prefetched one chunk ahead. One barrier removed from the reuse wait vs R6.

#define NPOINTS (8 * 256 * 256)
#define THREADS 128
#define CHUNKS 4
#define PTS_PER_BLOCK (THREADS * CHUNKS)        // 512
#define NBLOCKS (NPOINTS / PTS_PER_BLOCK)       // 1024

// ---- per-point math: 8 float4 components of the 32-float output row ----
__device__ __forceinline__ void sph_point(float x, float y, float z, float4 v[8]) {
    const float rho2 = fmaf(x, x, y * y);
    const float r2   = fmaf(z, z, rho2);
    const float rinv = rsqrtf(r2);
    const float ct   = z * rinv;                       // cos(theta)

    const bool  ok     = rho2 > 0.0f;
    const float rhoinv = ok ? rsqrtf(rho2) : 0.0f;
    const float st     = rho2 * rhoinv * rinv;         // sin(theta) = sqrt(rho2)/r
    const float c1 = ok ? x * rhoinv : 1.0f;
    const float s1 = y * rhoinv;
    const float c2 = c1 * c1 - s1 * s1;
    const float s2 = 2.0f * c1 * s1;
    const float c3 = c1 * c2 - s1 * s2;
    const float s3 = s1 * c2 + c1 * s2;

    const float ct2 = ct * ct;
    const float st2 = st * st;

    // Associated Legendre with Condon-Shortley phase (matches reference).
    const float b11 = 0.34549414947133547f * (-st);
    const float re1 = b11 * c1, im1 = b11 * s1;

    const float b21 = 0.25751613468215834f * (-3.0f * ct * st);
    const float re21 = b21 * c1, im21 = b21 * s1;
    const float b22 = 0.12875806734107764f * (3.0f * st2);
    const float re22 = b22 * c2, im22 = b22 * s2;

    const float b31 = 0.21545345607610053f * (-1.5f * st * (5.0f * ct2 - 1.0f));
    const float re31 = b31 * c1, im31 = b31 * s1;
    const float b32 = 0.06813236509755226f * (15.0f * ct * st2);
    const float re32 = b32 * c2, im32 = b32 * s2;
    const float b33 = 0.027814921575518937f * (-15.0f * st2 * st);
    const float re33 = b33 * c3, im33 = b33 * s3;

    const float y00 = 0.28209479177387814f;
    const float y10 = 0.48860251190291992f * ct;
    const float y20 = 0.63078313050504009f * 0.5f * (3.0f * ct2 - 1.0f);
    const float y30 = 0.74635266518023113f * 0.5f * ct * (5.0f * ct2 - 3.0f);

    v[0] = make_float4(y00, 0.0f, -re1, im1);
    v[1] = make_float4(y10, 0.0f, re1, im1);
    v[2] = make_float4(re22, -im22, -re21, im21);
    v[3] = make_float4(y20, 0.0f, re21, im21);
    v[4] = make_float4(re22, im22, -re33, im33);
    v[5] = make_float4(re32, -im32, -re31, im31);
    v[6] = make_float4(y30, 0.0f, re31, im31);
    v[7] = make_float4(re32, im32, re33, im33);
}

// ---- fast path: 4-chunk pipeline, double-buffered SW128 smem, deferred TMA waits ----
__global__ __launch_bounds__(THREADS) void sph_kernel_tma(
    const __grid_constant__ CUtensorMap tmap,
    const float* __restrict__ X) {
    // 2 buffers x 128 rows x 128B = 32KB, 1024B-aligned (SW128 atoms).
    __shared__ __align__(1024) float4 sm[2 * 128 * 8];

    const int tid = threadIdx.x;
    const int rot = tid & 7;
    const unsigned base = blockIdx.x * (unsigned)PTS_PER_BLOCK;

    // Prefetch chunk 0.
    float cx = X[3u * (base + tid) + 0];
    float cy = X[3u * (base + tid) + 1];
    float cz = X[3u * (base + tid) + 2];

#pragma unroll
    for (int c = 0; c < CHUNKS; c++) {
        // Prefetch next chunk's inputs before this chunk's math.
        float nx = 0.f, ny = 0.f, nz = 0.f;
        if (c + 1 < CHUNKS) {
            const unsigned pn = base + (c + 1) * THREADS + tid;
            nx = X[3u * pn + 0];
            ny = X[3u * pn + 1];
            nz = X[3u * pn + 2];
        }

        float4 v[8];
        sph_point(cx, cy, cz, v);
        cx = nx; cy = ny; cz = nz;

        // Buffer reuse: chunk c reuses the buffer chunk c-2 committed. Lane 0
        // waits for that group's smem reads to finish; the following
        // __syncthreads publishes "buffer free" to all warps. (The commit for
        // chunk c-2 happened after a __syncthreads, so every thread's view of
        // the group ordering is consistent — no leading barrier needed.)
        if (c >= 2) {
            if (tid == 0)
                asm volatile("cp.async.bulk.wait_group.read 1;" ::: "memory");
            __syncthreads();
        }

        // SW128 swizzled STS: row tid, slot q -> q ^ (tid&7); conflict-free.
        float4* row = sm + (c & 1) * 128 * 8 + tid * 8;
        row[0 ^ rot] = v[0];
        row[1 ^ rot] = v[1];
        row[2 ^ rot] = v[2];
        row[3 ^ rot] = v[3];
        row[4 ^ rot] = v[4];
        row[5 ^ rot] = v[5];
        row[6 ^ rot] = v[6];
        row[7 ^ rot] = v[7];

        asm volatile("fence.proxy.async.shared::cta;" ::: "memory");
        __syncthreads();

        if (tid == 0) {
            uint32_t saddr;
            asm("{ .reg .u64 t; cvta.to.shared.u64 t, %1; cvt.u32.u64 %0, t; }"
                : "=r"(saddr)
                : "l"((const void*)(sm + (c & 1) * 128 * 8)));
            const int row0 = (int)(base + c * THREADS);
            asm volatile(
                "cp.async.bulk.tensor.2d.global.shared::cta.tile.bulk_group "
                "[%0, {%1, %2}], [%3];"
                :: "l"(&tmap), "r"(0), "r"(row0), "r"(saddr)
                : "memory");
            asm volatile("cp.async.bulk.commit_group;" ::: "memory");
        }
    }

    // Drain remaining TMA reads of smem before CTA teardown.
    __syncthreads();
    if (tid == 0)
        asm volatile("cp.async.bulk.wait_group.read 0;" ::: "memory");
}

// ---- fallback path: proven R5 kernel (padded smem + coalesced STG) ----
__global__ __launch_bounds__(128) void sph_kernel_stg(const float* __restrict__ X,
                                                      float4* __restrict__ out) {
    __shared__ float4 smf[256 * 9];
    const int tid = threadIdx.x;
    const unsigned base = blockIdx.x * 256u;
    const unsigned pa = base + tid;
    const unsigned pb = pa + 128;

    const float xa = X[3u * pa + 0], ya = X[3u * pa + 1], za = X[3u * pa + 2];
    const float xb = X[3u * pb + 0], yb = X[3u * pb + 1], zb = X[3u * pb + 2];

    float4 va[8], vb[8];
    sph_point(xa, ya, za, va);
    sph_point(xb, yb, zb, vb);

#pragma unroll
    for (int q = 0; q < 8; q++) smf[tid * 9 + q] = va[q];
#pragma unroll
    for (int q = 0; q < 8; q++) smf[(tid + 128) * 9 + q] = vb[q];

    __syncthreads();

    float4* dst = out + (unsigned long long)base * 8ull;
#pragma unroll
    for (int i = 0; i < 16; i++) {
        const int idx = tid + i * 128;
        dst[idx] = smf[(idx >> 3) * 9 + (idx & 7)];
    }
}

typedef CUresult (*EncodeFn)(
    CUtensorMap*, CUtensorMapDataType, cuuint32_t, void*,
    const cuuint64_t*, const cuuint64_t*, const cuuint32_t*, const cuuint32_t*,
    CUtensorMapInterleave, CUtensorMapSwizzle, CUtensorMapL2promotion,
    CUtensorMapFloatOOBfill);

extern "C" void kernel_launch(void* const* d_in, const int* in_sizes, int n_in,
                              void* d_out, int out_size) {
    const float* X = (const float*)d_in[0];

    void* fn = nullptr;
    cudaDriverEntryPointQueryResult qst = cudaDriverEntryPointSymbolNotFound;
    cudaError_t qerr = cudaGetDriverEntryPointByVersion(
        "cuTensorMapEncodeTiled", &fn, 12000, cudaEnableDefault, &qst);

    bool tma_ok = false;
    CUtensorMap tmap;
    if (qerr == cudaSuccess && qst == cudaDriverEntryPointSuccess && fn != nullptr) {
        EncodeFn encode = (EncodeFn)fn;
        cuuint64_t dims[2]    = {32, (cuuint64_t)NPOINTS};  // 32 f32 per row
        cuuint64_t strides[1] = {128};                      // 128B row stride
        cuuint32_t box[2]     = {32, 128};                  // 16KB tile
        cuuint32_t estr[2]    = {1, 1};
        CUresult r = encode(&tmap, CU_TENSOR_MAP_DATA_TYPE_FLOAT32, 2, d_out,
                            dims, strides, box, estr,
                            CU_TENSOR_MAP_INTERLEAVE_NONE,
                            CU_TENSOR_MAP_SWIZZLE_128B,
                            CU_TENSOR_MAP_L2_PROMOTION_L2_128B,
                            CU_TENSOR_MAP_FLOAT_OOB_FILL_NONE);
        tma_ok = (r == CUDA_SUCCESS);
    }

    if (tma_ok) {
        sph_kernel_tma<<<NBLOCKS, THREADS>>>(tmap, X);
    } else {
        sph_kernel_stg<<<NPOINTS / 256, 128>>>(X, (float4*)d_out);
    }
}